// round 8
// baseline (speedup 1.0000x reference)
#include <cuda_runtime.h>
#include <cstdint>
#include <cstddef>

#define BATCH  256
#define SEQT   365
#define HID    256
#define INSZ   32
#define G4     1024
#define GROUPS 16          // batch groups (clusters)
#define CSIZE  8           // CTAs per cluster
#define BPG    16          // batches per group
#define UPC    32          // units per CTA
#define NB     (GROUPS * CSIZE)   // 128 CTAs
#define NT     256
#define NTX    256

typedef unsigned long long ull;

// ---------------- scratch ----------------------------------------------------
// xw: [t][group][b16][k=256 units][gate=4] floats, bias folded in (382 MB)
__device__ float g_xwp[(size_t)SEQT * GROUPS * BPG * HID * 4];
// h exchange: [buf][group][k][bpair] float2 (h for batches 2bp, 2bp+1)
__device__ float2 g_hgrp[2][GROUPS][HID][8];

// ---------------- f32x2 helpers ----------------------------------------------
__device__ __forceinline__ ull pack2(float lo, float hi) {
    ull r; asm("mov.b64 %0, {%1, %2};" : "=l"(r) : "f"(lo), "f"(hi)); return r;
}
__device__ __forceinline__ void unpack2(ull v, float& lo, float& hi) {
    asm("mov.b64 {%0, %1}, %2;" : "=f"(lo), "=f"(hi) : "l"(v));
}
__device__ __forceinline__ ull fma2(ull a, ull b, ull c) {
    ull d; asm("fma.rn.f32x2 %0, %1, %2, %3;" : "=l"(d) : "l"(a), "l"(b), "l"(c)); return d;
}
__device__ __forceinline__ float sigf(float x) { return 1.0f / (1.0f + __expf(-x)); }

#define CLUSTER_SYNC() do { \
    asm volatile("barrier.cluster.arrive.aligned;" ::: "memory"); \
    asm volatile("barrier.cluster.wait.aligned;"   ::: "memory"); \
} while (0)

// ============================================================================
// Kernel A: xw producer. grid (SEQT, 8): one t, 32-unit tile. thread = batch.
// Writes g_xwp[t][grp][b16][k][g] float4(f,i,o,g) via SMEM staging (coalesced).
// ============================================================================
__global__ void __launch_bounds__(NTX) xw_kernel(const float* __restrict__ x,
                                                 const float* __restrict__ w_ih,
                                                 const float* __restrict__ bias) {
    extern __shared__ char smx[];
    float* ws    = (float*)smx;                    // [k=32][ul=32][g=4], 16 KB
    float* stage = (float*)(smx + 16384);          // [b=256][132], pad row 132 floats

    const int t   = blockIdx.x;
    const int u00 = blockIdx.y * 32;
    const int tid = threadIdx.x;

    for (int i = tid; i < INSZ * 32 * 4; i += NTX) {
        int g = i & 3, ul = (i >> 2) & 31, k = i >> 7;
        ws[i] = w_ih[(size_t)k * G4 + g * HID + u00 + ul];
    }
    __syncthreads();

    const int b = tid;
    float xr[INSZ];
    const float4* xp = (const float4*)(x + ((size_t)b * SEQT + t) * INSZ);
#pragma unroll
    for (int q = 0; q < INSZ / 4; q++) {
        float4 v = xp[q];
        xr[4*q+0] = v.x; xr[4*q+1] = v.y; xr[4*q+2] = v.z; xr[4*q+3] = v.w;
    }

    float* srow = stage + b * 132;
    for (int ul = 0; ul < 32; ul++) {
        int u = u00 + ul;
        ull aFI = pack2(bias[u],         bias[HID + u]);
        ull aOG = pack2(bias[2*HID + u], bias[3*HID + u]);
#pragma unroll
        for (int k = 0; k < INSZ; k++) {
            float4 wv = *(const float4*)(ws + (k * 32 + ul) * 4);   // broadcast
            ull xk = pack2(xr[k], xr[k]);
            aFI = fma2(xk, pack2(wv.x, wv.y), aFI);
            aOG = fma2(xk, pack2(wv.z, wv.w), aOG);
        }
        float f, i_, o, g;
        unpack2(aFI, f, i_); unpack2(aOG, o, g);
        *(float4*)(srow + ul * 4) = make_float4(f, i_, o, g);
    }
    __syncthreads();

    // coalesced writeout: warp w handles rows b = w + 8r
    const int w = tid >> 5, lane = tid & 31;
    for (int r = 0; r < 32; r++) {
        int bb = w + 8 * r;
        float4 v = *(const float4*)(stage + bb * 132 + lane * 4);
        size_t dst = ((((size_t)t * GROUPS + (bb >> 4)) * BPG + (bb & 15)) * HID
                      + u00 + lane) * 4;
        __stcs((float4*)(g_xwp + dst), v);
    }
}

// ============================================================================
// Kernel B: persistent LSTM, clusters of 8 over batch groups.
// CTA (grp = bid>>3, rank = bid&7): w slice [256 k][128 cols] in SMEM,
// computes gates for 16 batches; h exchanged via L2 + cluster.sync.
// Compute: warp (g = w>>1, bhalf = w&1), lane = unit; acc = 4 bpairs (f32x2).
// Activation: warp = bpair, lane = unit; c in regs.
// ============================================================================
__global__ void __launch_bounds__(NT, 1) __cluster_dims__(CSIZE, 1, 1)
lstm_kernel(const float* __restrict__ w_hh,
            const float* __restrict__ fc_w,
            const float* __restrict__ fc_b,
            float* __restrict__ out) {
    extern __shared__ char sm[];
    float* w_s     = (float*)sm;                   // [128 cols][260], 133120 B
    ull*   h_s     = (ull*)(sm + 133120);          // [256 k][10] (pad), 20480 B
    ull*   gates_s = (ull*)(sm + 153600);          // [g][bp][u], 8192 B
    float* stage_h = (float*)(sm + 161792);        // [16 b][32 u], 2048 B
    float* stage_c = stage_h + BPG * UPC;          // 2048 B

    const int bid  = blockIdx.x;
    const int grp  = bid >> 3;
    const int rank = bid & 7;
    const int tid  = threadIdx.x;
    const int lane = tid & 31;
    const int w    = tid >> 5;
    const int g    = w >> 1;           // gate (compute phase)
    const int bh   = w & 1;            // batch half (compute phase)
    const int bp   = w;                // bpair (activation phase)
    const int kglob = rank * UPC + lane;

    // ---- load w slice: w_s[c][k], c = g*32+u, stride 260 (bank-spread) ----
    for (int i = tid; i < 128 * HID; i += NT) {
        int c = i & 127, k = i >> 7;
        w_s[c * 260 + k] = w_hh[(size_t)k * G4 + (c >> 5) * HID + rank * UPC + (c & 31)];
    }
    __syncthreads();

    float c0 = 0.0f, c1 = 0.0f;

    float* outO = out;
    float* outH = out + BATCH;
    float* outC = outH + (size_t)BATCH * SEQT * HID;

    // xw prefetch for t=0 (activation mapping: bp, lane)
    const size_t xw_t = (size_t)GROUPS * BPG * HID * 4;
    const float* xwb0 = g_xwp + (((size_t)grp * BPG + 2 * bp)     * HID + kglob) * 4;
    const float* xwb1 = g_xwp + (((size_t)grp * BPG + 2 * bp + 1) * HID + kglob) * 4;
    float4 xq0 = __ldcs((const float4*)xwb0);
    float4 xq1 = __ldcs((const float4*)xwb1);

    for (int t = 0; t < SEQT; t++) {
        // ---- compute gate sums over k (reads h_s, w_s) ----
        if (t > 0) {
            const float* wc = w_s + (g * 32 + lane) * 260;
            const ull*   hb = h_s + bh * 4;
            ull a0 = 0, a1 = 0, a2 = 0, a3 = 0;
#pragma unroll 4
            for (int kc = 0; kc < 64; kc++) {
                float4 wv = *(const float4*)(wc + kc * 4);
#pragma unroll
                for (int j = 0; j < 4; j++) {
                    const ull* hr = hb + (kc * 4 + j) * 10;
                    ulonglong2 hA = *(const ulonglong2*)(hr);
                    ulonglong2 hB = *(const ulonglong2*)(hr + 2);
                    float wj = (j == 0) ? wv.x : (j == 1) ? wv.y : (j == 2) ? wv.z : wv.w;
                    ull w2 = pack2(wj, wj);
                    a0 = fma2(hA.x, w2, a0);
                    a1 = fma2(hA.y, w2, a1);
                    a2 = fma2(hB.x, w2, a2);
                    a3 = fma2(hB.y, w2, a3);
                }
            }
            ull* gp = gates_s + (size_t)(g * 8 + bh * 4) * 32 + lane;
            gp[0]  = a0;
            gp[32] = a1;
            gp[64] = a2;
            gp[96] = a3;
        }
        __syncthreads();

        // ---- activation: thread = (bpair bp, unit lane) ----
        float sf0 = xq0.x, si0 = xq0.y, so0 = xq0.z, sg0 = xq0.w;
        float sf1 = xq1.x, si1 = xq1.y, so1 = xq1.z, sg1 = xq1.w;
        if (t > 0) {
            const ull* gp = gates_s + bp * 32 + lane;
            float p0, p1;
            unpack2(gp[0],   p0, p1); sf0 += p0; sf1 += p1;
            unpack2(gp[256], p0, p1); si0 += p0; si1 += p1;
            unpack2(gp[512], p0, p1); so0 += p0; so1 += p1;
            unpack2(gp[768], p0, p1); sg0 += p0; sg1 += p1;
        }
        if (t + 1 < SEQT) {
            xq0 = __ldcs((const float4*)(xwb0 + (size_t)(t + 1) * xw_t));
            xq1 = __ldcs((const float4*)(xwb1 + (size_t)(t + 1) * xw_t));
        }

        c0 = sigf(sf0) * c0 + sigf(si0) * tanhf(sg0);
        c1 = sigf(sf1) * c1 + sigf(si1) * tanhf(sg1);
        float h0 = sigf(so0) * tanhf(c0);
        float h1 = sigf(so1) * tanhf(c1);

        stage_h[(2 * bp) * 32 + lane]     = h0;
        stage_h[(2 * bp + 1) * 32 + lane] = h1;
        stage_c[(2 * bp) * 32 + lane]     = c0;
        stage_c[(2 * bp + 1) * 32 + lane] = c1;

        g_hgrp[(t + 1) & 1][grp][kglob][bp] = make_float2(h0, h1);

        CLUSTER_SYNC();   // h_grp complete group-wide; also CTA barrier for stage

        // ---- coalesced output writes from stage ----
        {
            int sel = tid >> 7;                 // 0: h, 1: c
            int i   = tid & 127;
            int b16 = i >> 3, q = i & 7;
            const float* src = (sel ? stage_c : stage_h) + b16 * 32 + q * 4;
            float4 v = *(const float4*)src;
            size_t bglob = (size_t)grp * BPG + b16;
            float* dst = (sel ? outC : outH) + (bglob * SEQT + t) * HID + rank * UPC + q * 4;
            __stcs((float4*)dst, v);
        }
        // ---- reload full group h into h_s (thread = k) ----
        {
            const float4* src = (const float4*)&g_hgrp[(t + 1) & 1][grp][tid][0];
            float4 v0 = __ldcg(src);
            float4 v1 = __ldcg(src + 1);
            float4 v2 = __ldcg(src + 2);
            float4 v3 = __ldcg(src + 3);
            ull* hd = h_s + tid * 10;
            *(float4*)(hd)     = v0;
            *(float4*)(hd + 2) = v1;
            *(float4*)(hd + 4) = v2;
            *(float4*)(hd + 6) = v3;
        }
        __syncthreads();
    }

    // ---- final FC: CTA computes batches 2*rank, 2*rank+1 of its group ----
    {
        float2* red2 = (float2*)stage_h;        // reuse stage (4 KB)
        float fw = fc_w[tid];
        float v0, v1;
        unpack2(h_s[tid * 10 + rank], v0, v1);
        red2[tid] = make_float2(v0 * fw, v1 * fw);
        __syncthreads();
        for (int s = NT / 2; s > 0; s >>= 1) {
            if (tid < s) {
                float2 a = red2[tid], bq = red2[tid + s];
                red2[tid] = make_float2(a.x + bq.x, a.y + bq.y);
            }
            __syncthreads();
        }
        if (tid == 0) {
            float fb = fc_b[0];
            int b0g = grp * BPG + 2 * rank;
            outO[b0g]     = red2[0].x + fb;
            outO[b0g + 1] = red2[0].y + fb;
        }
    }
}

// ============================================================================
extern "C" void kernel_launch(void* const* d_in, const int* in_sizes, int n_in,
                              void* d_out, int out_size) {
    const float* x    = (const float*)d_in[0];
    const float* w_ih = (const float*)d_in[1];
    const float* w_hh = (const float*)d_in[2];
    const float* bias = (const float*)d_in[3];
    const float* fc_w = (const float*)d_in[4];
    const float* fc_b = (const float*)d_in[5];
    float* out = (float*)d_out;

    static int configured = 0;
    if (!configured) {
        cudaFuncSetAttribute(xw_kernel,  cudaFuncAttributeMaxDynamicSharedMemorySize, 151552);
        cudaFuncSetAttribute(lstm_kernel, cudaFuncAttributeMaxDynamicSharedMemorySize, 165888);
        configured = 1;
    }

    dim3 gA(SEQT, 8);
    xw_kernel<<<gA, NTX, 151552>>>(x, w_ih, bias);
    lstm_kernel<<<NB, NT, 165888>>>(w_hh, fc_w, fc_b, out);
}

// round 9
// speedup vs baseline: 1.1624x; 1.1624x over previous
#include <cuda_runtime.h>
#include <cstdint>
#include <cstddef>

#define BATCH  256
#define SEQT   365
#define HID    256
#define INSZ   32
#define G4     1024
#define GROUPS 16          // batch groups (one 8-CTA cluster each)
#define CSIZE  8
#define BPG    16          // batches per group
#define UPC    32          // units per CTA (x4 gates = 128 gate-cols)
#define NB     (GROUPS * CSIZE)   // 128 CTAs
#define NT     256
#define NTX    256

typedef unsigned long long ull;

// ---------------- scratch ----------------------------------------------------
// xw: [t][group][b16][unit=256][gate=4] floats, bias folded in (382 MB)
__device__ float g_xwp[(size_t)SEQT * GROUPS * BPG * HID * 4];
// h exchange: [buf][group][k][b16] floats (64 B per k row)
__device__ float g_hgrp[2][GROUPS][HID][BPG];

// ---------------- f32x2 helpers ----------------------------------------------
__device__ __forceinline__ ull pack2(float lo, float hi) {
    ull r; asm("mov.b64 %0, {%1, %2};" : "=l"(r) : "f"(lo), "f"(hi)); return r;
}
__device__ __forceinline__ void unpack2(ull v, float& lo, float& hi) {
    asm("mov.b64 {%0, %1}, %2;" : "=f"(lo), "=f"(hi) : "l"(v));
}
__device__ __forceinline__ ull fma2(ull a, ull b, ull c) {
    ull d; asm("fma.rn.f32x2 %0, %1, %2, %3;" : "=l"(d) : "l"(a), "l"(b), "l"(c)); return d;
}
__device__ __forceinline__ ull add2(ull a, ull b) {
    ull d; asm("add.rn.f32x2 %0, %1, %2;" : "=l"(d) : "l"(a), "l"(b)); return d;
}
__device__ __forceinline__ float sigf(float x) { return 1.0f / (1.0f + __expf(-x)); }

#define CLUSTER_SYNC() do { \
    asm volatile("barrier.cluster.arrive.aligned;" ::: "memory"); \
    asm volatile("barrier.cluster.wait.aligned;"   ::: "memory"); \
} while (0)

// ============================================================================
// Kernel A: xw producer (validated in R8). grid (SEQT, 8). thread = batch.
// Writes g_xwp[t][grp][b16][unit][g] float4(f,i,o,g) via SMEM staging.
// ============================================================================
__global__ void __launch_bounds__(NTX) xw_kernel(const float* __restrict__ x,
                                                 const float* __restrict__ w_ih,
                                                 const float* __restrict__ bias) {
    extern __shared__ char smx[];
    float* ws    = (float*)smx;                    // [k=32][ul=32][g=4], 16 KB
    float* stage = (float*)(smx + 16384);          // [b=256][132]

    const int t   = blockIdx.x;
    const int u00 = blockIdx.y * 32;
    const int tid = threadIdx.x;

    for (int i = tid; i < INSZ * 32 * 4; i += NTX) {
        int g = i & 3, ul = (i >> 2) & 31, k = i >> 7;
        ws[i] = w_ih[(size_t)k * G4 + g * HID + u00 + ul];
    }
    __syncthreads();

    const int b = tid;
    float xr[INSZ];
    const float4* xp = (const float4*)(x + ((size_t)b * SEQT + t) * INSZ);
#pragma unroll
    for (int q = 0; q < INSZ / 4; q++) {
        float4 v = xp[q];
        xr[4*q+0] = v.x; xr[4*q+1] = v.y; xr[4*q+2] = v.z; xr[4*q+3] = v.w;
    }

    float* srow = stage + b * 132;
    for (int ul = 0; ul < 32; ul++) {
        int u = u00 + ul;
        ull aFI = pack2(bias[u],         bias[HID + u]);
        ull aOG = pack2(bias[2*HID + u], bias[3*HID + u]);
#pragma unroll
        for (int k = 0; k < INSZ; k++) {
            float4 wv = *(const float4*)(ws + (k * 32 + ul) * 4);
            ull xk = pack2(xr[k], xr[k]);
            aFI = fma2(xk, pack2(wv.x, wv.y), aFI);
            aOG = fma2(xk, pack2(wv.z, wv.w), aOG);
        }
        float f, i_, o, g;
        unpack2(aFI, f, i_); unpack2(aOG, o, g);
        *(float4*)(srow + ul * 4) = make_float4(f, i_, o, g);
    }
    __syncthreads();

    const int w = tid >> 5, lane = tid & 31;
    for (int r = 0; r < 32; r++) {
        int bb = w + 8 * r;
        float4 v = *(const float4*)(stage + bb * 132 + lane * 4);
        size_t dst = ((((size_t)t * GROUPS + (bb >> 4)) * BPG + (bb & 15)) * HID
                      + u00 + lane) * 4;
        __stcs((float4*)(g_xwp + dst), v);
    }
}

// ============================================================================
// Kernel B: persistent LSTM, 16 clusters of 8 over batch groups.
// CTA (grp, rank): w_s[k][u*4+g] = w_hh slice for units rank*32..+32 (128 KB).
// Compute: warp (kq = w>>1, bg = w&1); lane = unit. Per k: one conflict-free
//   LDS.128 (4 gate weights) + broadcast LDG.128x2 (8 batches' h, pre-paired)
//   -> 16 fma2. acc[bp 0..3][gate 0..3] f32x2 over batch pairs.
// Reduce over kq via gates_s; activation: warp = bpair, lane = unit; c in regs.
// ============================================================================
__global__ void __launch_bounds__(NT, 1) __cluster_dims__(CSIZE, 1, 1)
lstm_kernel(const float* __restrict__ w_hh,
            const float* __restrict__ fc_w,
            const float* __restrict__ fc_b,
            float* __restrict__ out) {
    extern __shared__ char sm[];
    float* w_s     = (float*)sm;                   // [256 k][128 c], 128 KB
    ull*   gates_s = (ull*)(sm + 131072);          // [kq][bp8][u32][g4], 32 KB

    const int bid  = blockIdx.x;
    const int grp  = bid >> 3;
    const int rank = bid & 7;
    const int tid  = threadIdx.x;
    const int lane = tid & 31;
    const int w    = tid >> 5;
    const int kq   = w >> 1;            // k-quarter (compute)
    const int bg   = w & 1;             // batch half-of-8 (compute)
    const int kglob = rank * UPC + lane;

    // ---- load w slice: w_s[k][u*4+g] ----
    for (int i = tid; i < 128 * HID; i += NT) {
        int c = i & 127, k = i >> 7;
        w_s[(size_t)k * 128 + c] =
            w_hh[(size_t)k * G4 + (c & 3) * HID + rank * UPC + (c >> 2)];
    }
    __syncthreads();

    float c0 = 0.0f, c1 = 0.0f;

    float* outO = out;
    float* outH = out + BATCH;
    float* outC = outH + (size_t)BATCH * SEQT * HID;

    // xw prefetch for t=0 (activation mapping: bp=w, unit=lane)
    const size_t xw_t = (size_t)GROUPS * BPG * HID * 4;
    const float* xwb0 = g_xwp + (((size_t)grp * BPG + 2 * w)     * HID + kglob) * 4;
    const float* xwb1 = g_xwp + (((size_t)grp * BPG + 2 * w + 1) * HID + kglob) * 4;
    float4 xq0 = __ldcs((const float4*)xwb0);
    float4 xq1 = __ldcs((const float4*)xwb1);

    for (int t = 0; t < SEQT; t++) {
        ull acc[4][4];
#pragma unroll
        for (int bp = 0; bp < 4; bp++)
#pragma unroll
            for (int g = 0; g < 4; g++) acc[bp][g] = 0;

        if (t > 0) {
            const int kb = kq * 64;
            const float* hbase = &g_hgrp[t & 1][grp][0][bg * 8];
            float4 hb4[2][8];                       // [buf][k-in-chunk*2 + half]
#pragma unroll
            for (int j = 0; j < 4; j++) {
                const float4* p = (const float4*)(hbase + (size_t)(kb + j) * BPG);
                hb4[0][j*2]   = __ldcg(p);
                hb4[0][j*2+1] = __ldcg(p + 1);
            }
#pragma unroll 2
            for (int ch = 0; ch < 16; ch++) {
                const int cur = ch & 1;
                if (ch < 15) {
#pragma unroll
                    for (int j = 0; j < 4; j++) {
                        const float4* p = (const float4*)
                            (hbase + (size_t)(kb + (ch + 1) * 4 + j) * BPG);
                        hb4[cur ^ 1][j*2]   = __ldcg(p);
                        hb4[cur ^ 1][j*2+1] = __ldcg(p + 1);
                    }
                }
#pragma unroll
                for (int j = 0; j < 4; j++) {
                    const int k = kb + ch * 4 + j;
                    float4 wv = *(const float4*)(w_s + (size_t)k * 128 + lane * 4);
                    ull wf = pack2(wv.x, wv.x);
                    ull wi = pack2(wv.y, wv.y);
                    ull wo = pack2(wv.z, wv.z);
                    ull wg = pack2(wv.w, wv.w);
                    ulonglong2 h01 = *(ulonglong2*)&hb4[cur][j*2];      // (b0,b1),(b2,b3)
                    ulonglong2 h23 = *(ulonglong2*)&hb4[cur][j*2+1];    // (b4,b5),(b6,b7)
                    acc[0][0] = fma2(h01.x, wf, acc[0][0]);
                    acc[0][1] = fma2(h01.x, wi, acc[0][1]);
                    acc[0][2] = fma2(h01.x, wo, acc[0][2]);
                    acc[0][3] = fma2(h01.x, wg, acc[0][3]);
                    acc[1][0] = fma2(h01.y, wf, acc[1][0]);
                    acc[1][1] = fma2(h01.y, wi, acc[1][1]);
                    acc[1][2] = fma2(h01.y, wo, acc[1][2]);
                    acc[1][3] = fma2(h01.y, wg, acc[1][3]);
                    acc[2][0] = fma2(h23.x, wf, acc[2][0]);
                    acc[2][1] = fma2(h23.x, wi, acc[2][1]);
                    acc[2][2] = fma2(h23.x, wo, acc[2][2]);
                    acc[2][3] = fma2(h23.x, wg, acc[2][3]);
                    acc[3][0] = fma2(h23.y, wf, acc[3][0]);
                    acc[3][1] = fma2(h23.y, wi, acc[3][1]);
                    acc[3][2] = fma2(h23.y, wo, acc[3][2]);
                    acc[3][3] = fma2(h23.y, wg, acc[3][3]);
                }
            }
        }

        // ---- store partials: gates_s[kq][bg*4+bp][lane][g] ----
        {
            ull* gp = gates_s + ((size_t)(kq * 8 + bg * 4) * 32 + lane) * 4;
#pragma unroll
            for (int bp = 0; bp < 4; bp++) {
                *(ulonglong2*)(gp + (size_t)bp * 128)     =
                    make_ulonglong2(acc[bp][0], acc[bp][1]);
                *(ulonglong2*)(gp + (size_t)bp * 128 + 2) =
                    make_ulonglong2(acc[bp][2], acc[bp][3]);
            }
        }
        __syncthreads();

        // ---- activation: thread = (bpair w, unit lane) ----
        ull sF = 0, sI = 0, sO = 0, sG = 0;
        if (t > 0) {
#pragma unroll
            for (int q = 0; q < 4; q++) {
                const ull* gp = gates_s + ((size_t)(q * 8 + w) * 32 + lane) * 4;
                ulonglong2 a = *(const ulonglong2*)gp;
                ulonglong2 bq = *(const ulonglong2*)(gp + 2);
                sF = add2(sF, a.x);
                sI = add2(sI, a.y);
                sO = add2(sO, bq.x);
                sG = add2(sG, bq.y);
            }
        }
        float pf0, pf1, pi0, pi1, po0, po1, pg0, pg1;
        unpack2(sF, pf0, pf1); unpack2(sI, pi0, pi1);
        unpack2(sO, po0, po1); unpack2(sG, pg0, pg1);
        float sf0 = xq0.x + pf0, si0 = xq0.y + pi0, so0 = xq0.z + po0, sg0 = xq0.w + pg0;
        float sf1 = xq1.x + pf1, si1 = xq1.y + pi1, so1 = xq1.z + po1, sg1 = xq1.w + pg1;

        if (t + 1 < SEQT) {
            xq0 = __ldcs((const float4*)(xwb0 + (size_t)(t + 1) * xw_t));
            xq1 = __ldcs((const float4*)(xwb1 + (size_t)(t + 1) * xw_t));
        }

        c0 = sigf(sf0) * c0 + sigf(si0) * tanhf(sg0);
        c1 = sigf(sf1) * c1 + sigf(si1) * tanhf(sg1);
        float h0 = sigf(so0) * tanhf(c0);
        float h1 = sigf(so1) * tanhf(c1);

        // h exchange (group-wide via L2) + outputs
        *(float2*)&g_hgrp[(t + 1) & 1][grp][kglob][2 * w] = make_float2(h0, h1);

        {
            size_t b0g = (size_t)grp * BPG + 2 * w;
            size_t o0 = (b0g * SEQT + t) * HID + kglob;
            size_t o1 = ((b0g + 1) * SEQT + t) * HID + kglob;
            __stcs(outH + o0, h0);
            __stcs(outH + o1, h1);
            __stcs(outC + o0, c0);
            __stcs(outC + o1, c1);
        }

        CLUSTER_SYNC();
    }

    // ---- final FC: CTA rank computes batches 2*rank, 2*rank+1 of its group ----
    {
        float2* red2 = (float2*)gates_s;       // reuse (needs 2 KB)
        float fw = fc_w[tid];
        float2 hv = *(const float2*)&g_hgrp[SEQT & 1][grp][tid][2 * rank];
        red2[tid] = make_float2(hv.x * fw, hv.y * fw);
        __syncthreads();
        for (int s = NT / 2; s > 0; s >>= 1) {
            if (tid < s) {
                float2 a = red2[tid], bq = red2[tid + s];
                red2[tid] = make_float2(a.x + bq.x, a.y + bq.y);
            }
            __syncthreads();
        }
        if (tid == 0) {
            float fb = fc_b[0];
            int b0g = grp * BPG + 2 * rank;
            outO[b0g]     = red2[0].x + fb;
            outO[b0g + 1] = red2[0].y + fb;
        }
    }
}

// ============================================================================
extern "C" void kernel_launch(void* const* d_in, const int* in_sizes, int n_in,
                              void* d_out, int out_size) {
    const float* x    = (const float*)d_in[0];
    const float* w_ih = (const float*)d_in[1];
    const float* w_hh = (const float*)d_in[2];
    const float* bias = (const float*)d_in[3];
    const float* fc_w = (const float*)d_in[4];
    const float* fc_b = (const float*)d_in[5];
    float* out = (float*)d_out;

    static int configured = 0;
    if (!configured) {
        cudaFuncSetAttribute(xw_kernel,   cudaFuncAttributeMaxDynamicSharedMemorySize, 151552);
        cudaFuncSetAttribute(lstm_kernel, cudaFuncAttributeMaxDynamicSharedMemorySize, 163840);
        configured = 1;
    }

    dim3 gA(SEQT, 8);
    xw_kernel<<<gA, NTX, 151552>>>(x, w_ih, bias);
    lstm_kernel<<<NB, NT, 163840>>>(w_hh, fc_w, fc_b, out);
}

// round 10
// speedup vs baseline: 1.7696x; 1.5224x over previous
#include <cuda_runtime.h>
#include <cstdint>
#include <cstddef>

#define BATCH  256
#define SEQT   365
#define HID    256
#define INSZ   32
#define G4     1024
#define NB     128
#define NT     256
#define NTX    256
#define NGRP   8            // batch groups (32 b each), independent barriers
#define UGRP   16           // unit groups (16 u each)

typedef unsigned long long ull;

// ---------------- scratch ----------------------------------------------------
// xw: [t][b=256][unit=256][gate=4] floats (f,i,o,g), bias folded in (382 MB)
__device__ float g_xwp[(size_t)SEQT * BATCH * HID * 4];
// h exchange: [buf][unit=256][batch=256] floats
__device__ float g_hx[2][HID * BATCH];
// per-group barriers, count/gen on separate 128B lines
__device__ unsigned g_cnt[NGRP * 32];
__device__ unsigned g_gen[NGRP * 32];

// ---------------- f32x2 helpers ----------------------------------------------
__device__ __forceinline__ ull pack2(float lo, float hi) {
    ull r; asm("mov.b64 %0, {%1, %2};" : "=l"(r) : "f"(lo), "f"(hi)); return r;
}
__device__ __forceinline__ void unpack2(ull v, float& lo, float& hi) {
    asm("mov.b64 {%0, %1}, %2;" : "=f"(lo), "=f"(hi) : "l"(v));
}
__device__ __forceinline__ ull fma2(ull a, ull b, ull c) {
    ull d; asm("fma.rn.f32x2 %0, %1, %2, %3;" : "=l"(d) : "l"(a), "l"(b), "l"(c)); return d;
}
__device__ __forceinline__ ull add2(ull a, ull b) {
    ull d; asm("add.rn.f32x2 %0, %1, %2;" : "=l"(d) : "l"(a), "l"(b)); return d;
}
__device__ __forceinline__ float sigf(float x) { return 1.0f / (1.0f + __expf(-x)); }

// ---------------- per-group barrier (16 CTAs; R7-proven pattern) --------------
__device__ __forceinline__ void group_barrier(int bg) {
    __syncthreads();
    if (threadIdx.x == 0) {
        volatile unsigned* genp = &g_gen[bg * 32];
        unsigned gen = *genp;
        __threadfence();
        if (atomicAdd(&g_cnt[bg * 32], 1u) == UGRP - 1u) {
            g_cnt[bg * 32] = 0;
            __threadfence();
            *genp = gen + 1u;
        } else {
            while (*genp == gen) { }
        }
    }
    __syncthreads();
}

// ============================================================================
// Kernel A: xw producer. grid (SEQT, 8). thread = batch.
// Writes g_xwp[t][b][unit][g] float4(f,i,o,g) via SMEM staging (coalesced).
// ============================================================================
__global__ void __launch_bounds__(NTX) xw_kernel(const float* __restrict__ x,
                                                 const float* __restrict__ w_ih,
                                                 const float* __restrict__ bias) {
    extern __shared__ char smx[];
    float* ws    = (float*)smx;                    // [k=32][ul=32][g=4], 16 KB
    float* stage = (float*)(smx + 16384);          // [b=256][132]

    const int t   = blockIdx.x;
    const int u00 = blockIdx.y * 32;
    const int tid = threadIdx.x;

    for (int i = tid; i < INSZ * 32 * 4; i += NTX) {
        int g = i & 3, ul = (i >> 2) & 31, k = i >> 7;
        ws[i] = w_ih[(size_t)k * G4 + g * HID + u00 + ul];
    }
    __syncthreads();

    const int b = tid;
    float xr[INSZ];
    const float4* xp = (const float4*)(x + ((size_t)b * SEQT + t) * INSZ);
#pragma unroll
    for (int q = 0; q < INSZ / 4; q++) {
        float4 v = xp[q];
        xr[4*q+0] = v.x; xr[4*q+1] = v.y; xr[4*q+2] = v.z; xr[4*q+3] = v.w;
    }

    float* srow = stage + b * 132;
    for (int ul = 0; ul < 32; ul++) {
        int u = u00 + ul;
        ull aFI = pack2(bias[u],         bias[HID + u]);
        ull aOG = pack2(bias[2*HID + u], bias[3*HID + u]);
#pragma unroll
        for (int k = 0; k < INSZ; k++) {
            float4 wv = *(const float4*)(ws + (k * 32 + ul) * 4);
            ull xk = pack2(xr[k], xr[k]);
            aFI = fma2(xk, pack2(wv.x, wv.y), aFI);
            aOG = fma2(xk, pack2(wv.z, wv.w), aOG);
        }
        float f, i_, o, g;
        unpack2(aFI, f, i_); unpack2(aOG, o, g);
        *(float4*)(srow + ul * 4) = make_float4(f, i_, o, g);
    }
    __syncthreads();

    const int w = tid >> 5, lane = tid & 31;
    for (int r = 0; r < 32; r++) {
        int bb = w + 8 * r;
        float4 v = *(const float4*)(stage + bb * 132 + lane * 4);
        size_t dst = ((size_t)(t * BATCH + bb) * HID + u00 + lane) * 4;
        __stcs((float4*)(g_xwp + dst), v);
    }
}

// ============================================================================
// Kernel B: persistent LSTM. CTA (ug = bid&15, bg = bid>>4):
//   units  u_base = ug*16 .. +16   (w slice 64 KB in SMEM, gate-pair packed)
//   batches b_base = bg*32 .. +32  (h working set 32 KB staged to SMEM/step)
// Compute warp: uh = w&1 (up-half), kq = w>>1 (k-quarter). Lane: up2 = l>>3,
//   b8 = l&7. Per k: 1 h-LDS.128 (4 b) + 2 w-LDS.128 (8 cols pre-paired) ->
//   16 fma2. acc[4 b][4 gates] f32x2 over (u0,u1).
// Reduce over kq via SMEM; activation thread = (bl = tid>>3, up = tid&7).
// ============================================================================
__global__ void __launch_bounds__(NT, 1)
lstm_kernel(const float* __restrict__ w_hh,
            const float* __restrict__ fc_w,
            const float* __restrict__ fc_b,
            float* __restrict__ out) {
    extern __shared__ char sm[];
    float* w_s     = (float*)sm;                   // [256 k][64 c], 64 KB
    char*  h_s     = sm + 65536;                   // [256 k][128 B] swizzled, 32 KB
    ull*   gates_s = (ull*)(sm + 98304);           // [kq][bl 32][up 8][g 4], 32 KB

    const int bid    = blockIdx.x;
    const int ug     = bid & 15;
    const int bg     = bid >> 4;
    const int u_base = ug * 16;
    const int b_base = bg * 32;
    const int tid    = threadIdx.x;
    const int l      = tid & 31;
    const int w      = tid >> 5;
    const int uh     = w & 1;
    const int kq     = w >> 1;
    const int up2    = l >> 3;
    const int b8     = l & 7;
    const int up_c   = uh * 4 + up2;     // compute-phase unit-pair (0..7)
    const int kb     = kq * 64;
    // activation-phase mapping
    const int bl     = tid >> 3;         // 0..31
    const int up_a   = tid & 7;          // 0..7
    const int b_act  = b_base + bl;
    const int u0     = u_base + up_a * 2;

    // ---- load w slice: w_s[k][up*8 + g*2 + u2] ----
    for (int i = tid; i < HID * 64; i += NT) {
        int k = i >> 6, c = i & 63;
        w_s[i] = w_hh[(size_t)k * G4 + ((c >> 1) & 3) * HID
                      + u_base + (c >> 3) * 2 + (c & 1)];
    }
    __syncthreads();

    float c0 = 0.0f, c1 = 0.0f;

    float* outO = out;
    float* outH = out + BATCH;
    float* outC = outH + (size_t)BATCH * SEQT * HID;

    // xw prefetch for t = 0
    const size_t xw_t = (size_t)BATCH * HID * 4;
    const float* xwb = g_xwp + ((size_t)b_act * HID + u0) * 4;
    float4 xq0 = __ldcs((const float4*)xwb);
    float4 xq1 = __ldcs((const float4*)xwb + 1);

    for (int t = 0; t < SEQT; t++) {
        if (t > 0) {
            // ---- stage h[all k][b_base..+32] into swizzled SMEM ----
            const float* gp = g_hx[t & 1] + (size_t)tid * BATCH + b_base;
            float4 hv[8];
#pragma unroll
            for (int j = 0; j < 8; j++) hv[j] = __ldcg((const float4*)gp + j);
            char* hrow = h_s + tid * 128;
            const int sw = (tid & 7) * 16;
#pragma unroll
            for (int j = 0; j < 8; j++)
                *(float4*)(hrow + ((j * 16) ^ sw)) = hv[j];
            __syncthreads();

            // ---- k-loop from SMEM ----
            ull acc[4][4];
#pragma unroll
            for (int j = 0; j < 4; j++)
#pragma unroll
                for (int g = 0; g < 4; g++) acc[j][g] = 0;

            const int hsel = b8 * 16;
#pragma unroll 8
            for (int kk = 0; kk < 64; kk++) {
                const int k = kb + kk;
                float4 hv4 = *(const float4*)(h_s + k * 128 + (hsel ^ ((k & 7) * 16)));
                const float* wp = w_s + k * 64 + up_c * 8;
                ulonglong2 wFI = *(const ulonglong2*)wp;        // (f0,f1),(i0,i1)
                ulonglong2 wOG = *(const ulonglong2*)(wp + 4);  // (o0,o1),(g0,g1)
                ull hx;
                hx = pack2(hv4.x, hv4.x);
                acc[0][0] = fma2(hx, wFI.x, acc[0][0]);
                acc[0][1] = fma2(hx, wFI.y, acc[0][1]);
                acc[0][2] = fma2(hx, wOG.x, acc[0][2]);
                acc[0][3] = fma2(hx, wOG.y, acc[0][3]);
                hx = pack2(hv4.y, hv4.y);
                acc[1][0] = fma2(hx, wFI.x, acc[1][0]);
                acc[1][1] = fma2(hx, wFI.y, acc[1][1]);
                acc[1][2] = fma2(hx, wOG.x, acc[1][2]);
                acc[1][3] = fma2(hx, wOG.y, acc[1][3]);
                hx = pack2(hv4.z, hv4.z);
                acc[2][0] = fma2(hx, wFI.x, acc[2][0]);
                acc[2][1] = fma2(hx, wFI.y, acc[2][1]);
                acc[2][2] = fma2(hx, wOG.x, acc[2][2]);
                acc[2][3] = fma2(hx, wOG.y, acc[2][3]);
                hx = pack2(hv4.w, hv4.w);
                acc[3][0] = fma2(hx, wFI.x, acc[3][0]);
                acc[3][1] = fma2(hx, wFI.y, acc[3][1]);
                acc[3][2] = fma2(hx, wOG.x, acc[3][2]);
                acc[3][3] = fma2(hx, wOG.y, acc[3][3]);
            }

            // ---- partials: gates_s[kq][b8*4+j][up_c][g] ----
#pragma unroll
            for (int j = 0; j < 4; j++) {
                ull* gpp = gates_s + ((size_t)(kq * 32 + b8 * 4 + j) * 8 + up_c) * 4;
                *(ulonglong2*)gpp       = make_ulonglong2(acc[j][0], acc[j][1]);
                *(ulonglong2*)(gpp + 2) = make_ulonglong2(acc[j][2], acc[j][3]);
            }
        }
        __syncthreads();

        // ---- activation: thread = (bl, up_a) ----
        float sf0 = xq0.x, si0 = xq0.y, so0 = xq0.z, sg0 = xq0.w;
        float sf1 = xq1.x, si1 = xq1.y, so1 = xq1.z, sg1 = xq1.w;
        if (t > 0) {
            ull sF = 0, sI = 0, sO = 0, sG = 0;
#pragma unroll
            for (int q = 0; q < 4; q++) {
                const ull* gpp = gates_s + ((size_t)(q * 32 + bl) * 8 + up_a) * 4;
                ulonglong2 a  = *(const ulonglong2*)gpp;
                ulonglong2 bq = *(const ulonglong2*)(gpp + 2);
                sF = add2(sF, a.x);
                sI = add2(sI, a.y);
                sO = add2(sO, bq.x);
                sG = add2(sG, bq.y);
            }
            float p0, p1;
            unpack2(sF, p0, p1); sf0 += p0; sf1 += p1;
            unpack2(sI, p0, p1); si0 += p0; si1 += p1;
            unpack2(sO, p0, p1); so0 += p0; so1 += p1;
            unpack2(sG, p0, p1); sg0 += p0; sg1 += p1;
        }
        if (t + 1 < SEQT) {
            xq0 = __ldcs((const float4*)(xwb + (size_t)(t + 1) * xw_t));
            xq1 = __ldcs((const float4*)(xwb + (size_t)(t + 1) * xw_t) + 1);
        }

        c0 = sigf(sf0) * c0 + sigf(si0) * tanhf(sg0);
        c1 = sigf(sf1) * c1 + sigf(si1) * tanhf(sg1);
        float h0 = sigf(so0) * tanhf(c0);
        float h1 = sigf(so1) * tanhf(c1);

        // h exchange (tiny: 2 KB per CTA)
        float* hx = g_hx[(t + 1) & 1];
        __stcg(hx + (size_t)u0 * BATCH + b_act, h0);
        __stcg(hx + (size_t)(u0 + 1) * BATCH + b_act, h1);

        // outputs: per (b, t): this CTA's 16 units -> 64B contiguous segments
        size_t ob = ((size_t)b_act * SEQT + t) * HID + u0;
        __stcs((float2*)(outH + ob), make_float2(h0, h1));
        __stcs((float2*)(outC + ob), make_float2(c0, c1));

        group_barrier(bg);
    }

    // ---- final FC (ug == 0 CTAs only): out[b] for this bg's 32 batches ----
    if (ug == 0) {
        float* gf = (float*)gates_s;           // reuse as [32 b][8] float scratch
        const int s = tid & 7;                 // k-slice of 32
        const int bb = tid >> 3;
        const float* hl = g_hx[SEQT & 1];
        float acc = 0.0f;
        for (int u = s * 32; u < s * 32 + 32; u++)
            acc += __ldcg(hl + (size_t)u * BATCH + b_base + bb) * fc_w[u];
        gf[bb * 8 + s] = acc;
        __syncthreads();
        if (s == 0) {
            float v = gf[bb * 8];
            for (int q = 1; q < 8; q++) v += gf[bb * 8 + q];
            outO[b_base + bb] = v + fc_b[0];
        }
    }
}

// ============================================================================
extern "C" void kernel_launch(void* const* d_in, const int* in_sizes, int n_in,
                              void* d_out, int out_size) {
    const float* x    = (const float*)d_in[0];
    const float* w_ih = (const float*)d_in[1];
    const float* w_hh = (const float*)d_in[2];
    const float* bias = (const float*)d_in[3];
    const float* fc_w = (const float*)d_in[4];
    const float* fc_b = (const float*)d_in[5];
    float* out = (float*)d_out;

    static int configured = 0;
    if (!configured) {
        cudaFuncSetAttribute(xw_kernel,   cudaFuncAttributeMaxDynamicSharedMemorySize, 151552);
        cudaFuncSetAttribute(lstm_kernel, cudaFuncAttributeMaxDynamicSharedMemorySize, 135168);
        configured = 1;
    }

    dim3 gA(SEQT, 8);
    xw_kernel<<<gA, NTX, 151552>>>(x, w_ih, bias);
    lstm_kernel<<<NB, NT, 135168>>>(w_hh, fc_w, fc_b, out);
}

// round 11
// speedup vs baseline: 2.2376x; 1.2645x over previous
#include <cuda_runtime.h>
#include <cstdint>
#include <cstddef>

#define BATCH 256
#define SEQT  365
#define HID   256
#define INSZ  32
#define G4    1024          // 4*HID
#define NB    128           // persistent blocks
#define NT    256           // lstm threads: 8 warps = 2 b-halves x 4 k-quarters
#define NTX   256           // xw_kernel threads
#define NPAIR (HID / 2)     // 128 unit pairs

typedef unsigned long long ull;

// ---------------- scratch (static device allocations; no cudaMalloc) ----------
// xw packed per unit-pair: [t][pair][2][b] float4
//   slot 0 = (f0,f1,i0,i1), slot 1 = (o0,o1,g0,g1), bias folded in. 382 MB.
__device__ float4 g_xw4[(size_t)SEQT * NPAIR * 2 * BATCH];
// hidden state, double buffered, [buf][k][b] floats (b contiguous)
__device__ float g_hb[2][HID * BATCH];
__device__ unsigned g_bar_count;
__device__ unsigned g_bar_gen;

// ---------------- packed f32x2 helpers (PTX-only; ptxas won't auto-fuse) ------
__device__ __forceinline__ ull pack2(float lo, float hi) {
    ull r;
    asm("mov.b64 %0, {%1, %2};" : "=l"(r) : "f"(lo), "f"(hi));
    return r;
}
__device__ __forceinline__ void unpack2(ull v, float& lo, float& hi) {
    asm("mov.b64 {%0, %1}, %2;" : "=f"(lo), "=f"(hi) : "l"(v));
}
__device__ __forceinline__ ull fma2(ull a, ull b, ull c) {
    ull d;
    asm("fma.rn.f32x2 %0, %1, %2, %3;" : "=l"(d) : "l"(a), "l"(b), "l"(c));
    return d;
}
__device__ __forceinline__ ull add2(ull a, ull b) {
    ull d;
    asm("add.rn.f32x2 %0, %1, %2;" : "=l"(d) : "l"(a), "l"(b));
    return d;
}
// fast sigmoid / tanh via MUFU.EX2 + RCP; saturate correctly at +/-inf
__device__ __forceinline__ float sigf(float x) {
    return __fdividef(1.0f, 1.0f + __expf(-x));
}
__device__ __forceinline__ float tanhf_fast(float x) {
    float e = __expf(2.0f * x);                  // 0 .. inf
    return 1.0f - __fdividef(2.0f, e + 1.0f);    // -1 .. 1
}

__device__ __forceinline__ unsigned swz(unsigned off) {   // SW128-style bank spread
    return off ^ ((off >> 3) & 0x70);
}

// ============================================================================
// Kernel A: xw. grid (SEQT, 8); block = one t, a 32-unit tile (16 pairs).
// Output layout matches lstm reader: g_xw4[t][pair][slot][b].
// ============================================================================
__global__ void __launch_bounds__(NTX) xw_kernel(const float* __restrict__ x,
                                                 const float* __restrict__ w_ih,
                                                 const float* __restrict__ bias) {
    __shared__ float ws[INSZ][16][8];     // [k][pair_local][c]
    const int t   = blockIdx.x;
    const int u00 = blockIdx.y * 32;
    const int tid = threadIdx.x;

    for (int i = tid; i < INSZ * 128; i += NTX) {
        int k = i >> 7, r = i & 127, p = r >> 3, c = r & 7;
        int unit = u00 + 2 * p + (c & 1);
        ws[k][p][c] = w_ih[(size_t)k * G4 + (c >> 1) * HID + unit];
    }
    __syncthreads();

    const int b = tid;
    ull xk2[INSZ];
    const float4* xp = (const float4*)(x + ((size_t)b * SEQT + t) * INSZ);
#pragma unroll
    for (int q = 0; q < INSZ / 4; q++) {
        float4 v = xp[q];
        xk2[4 * q + 0] = pack2(v.x, v.x);
        xk2[4 * q + 1] = pack2(v.y, v.y);
        xk2[4 * q + 2] = pack2(v.z, v.z);
        xk2[4 * q + 3] = pack2(v.w, v.w);
    }

    for (int p = 0; p < 16; p++) {
        int u = u00 + 2 * p;
        ull aF = pack2(bias[u],           bias[u + 1]);
        ull aI = pack2(bias[HID + u],     bias[HID + u + 1]);
        ull aO = pack2(bias[2 * HID + u], bias[2 * HID + u + 1]);
        ull aG = pack2(bias[3 * HID + u], bias[3 * HID + u + 1]);
#pragma unroll
        for (int k = 0; k < INSZ; k++) {
            ulonglong2 wA = *(const ulonglong2*)(&ws[k][p][0]);
            ulonglong2 wB = *(const ulonglong2*)(&ws[k][p][4]);
            aF = fma2(xk2[k], wA.x, aF);
            aI = fma2(xk2[k], wA.y, aI);
            aO = fma2(xk2[k], wB.x, aO);
            aG = fma2(xk2[k], wB.y, aG);
        }
        float f0, f1, i0, i1, o0, o1, g0, g1;
        unpack2(aF, f0, f1); unpack2(aI, i0, i1);
        unpack2(aO, o0, o1); unpack2(aG, g0, g1);
        size_t base = (((size_t)t * NPAIR + (u00 / 2 + p)) * 2) * BATCH + b;
        __stcs(&g_xw4[base],         make_float4(f0, f1, i0, i1));
        __stcs(&g_xw4[base + BATCH], make_float4(o0, o1, g0, g1));
    }
}

// ============================================================================
// Kernel B: persistent recurrent LSTM, batch-register-tiled (R7-proven),
// with arrive-early split barrier: output stores overlap the barrier wait.
// CTA owns units u0=2*bid, u0+1 (8 gate cols = 4 f32x2 pairs).
// Warp w: bh = w&1 (b-half of 128), kh = w>>1 (k-quarter of 64).
// Lane l:  bg = l>>1 (8-batch group), cg = l&1 (pair group: {f,i} or {o,g}).
// ============================================================================
__global__ void __launch_bounds__(NT, 1) lstm_kernel(const float* __restrict__ w_hh,
                                                     const float* __restrict__ fc_w,
                                                     const float* __restrict__ fc_b,
                                                     float* __restrict__ out) {
    __shared__ float ws[HID][8];            // [k][c], c = pair*2 + half, 8 KB
    __shared__ ull sm_part[4 * BATCH * 4];  // [kh][b][pair] swizzled, 32 KB
    __shared__ float redf[NT];

    const int bid = blockIdx.x;
    const int tid = threadIdx.x;
    const int u0  = bid * 2;
    const int w   = tid >> 5;
    const int l   = tid & 31;
    const int bh  = w & 1;
    const int kh  = w >> 1;              // 0..3
    const int bg  = l >> 1;              // 0..15
    const int cg  = l & 1;               // 0..1
    const int b0  = bh * 128 + bg * 8;   // lane's first batch
    const int kb  = kh * 64;             // lane's first k
    const int b   = tid;                 // activation-phase batch

    for (int i = tid; i < HID * 8; i += NT) {
        int k = i >> 3, c = i & 7;
        ws[k][c] = w_hh[(size_t)k * G4 + (c >> 1) * HID + u0 + (c & 1)];
    }
    __syncthreads();

    float cc0 = 0.0f, cc1 = 0.0f;

    float* outO = out;
    float* outH = out + BATCH;
    float* outC = outH + (size_t)BATCH * SEQT * HID;

    // xw prefetch for t = 0 (every thread, b = tid)
    const size_t xw_stride_t = (size_t)NPAIR * 2 * BATCH;
    const float4* xwp = g_xw4 + (size_t)bid * 2 * BATCH + b;
    float4 xA = __ldcs(xwp);
    float4 xB = __ldcs(xwp + BATCH);

    const int hoff4 = bh * 32 + bg * 2;  // float4 offset of lane's 8 batches

    for (int t = 0; t < SEQT; t++) {
        ull acc[8][2];
#pragma unroll
        for (int bb = 0; bb < 8; bb++) { acc[bb][0] = 0; acc[bb][1] = 0; }

        if (t > 0) {
            const float4* hp4 = (const float4*)g_hb[t & 1] + hoff4;
            float4 hA[2][4], hB[2][4];
#pragma unroll
            for (int j = 0; j < 4; j++) {
                hA[0][j] = __ldcg(hp4 + (size_t)(kb + j) * 64);
                hB[0][j] = __ldcg(hp4 + (size_t)(kb + j) * 64 + 1);
            }
#pragma unroll
            for (int ch = 0; ch < 16; ch++) {        // 16 chunks x 4 k = 64 k
                const int cur = ch & 1, nxt = cur ^ 1;
                if (ch < 15) {
#pragma unroll
                    for (int j = 0; j < 4; j++) {
                        hA[nxt][j] = __ldcg(hp4 + (size_t)(kb + (ch + 1) * 4 + j) * 64);
                        hB[nxt][j] = __ldcg(hp4 + (size_t)(kb + (ch + 1) * 4 + j) * 64 + 1);
                    }
                }
#pragma unroll
                for (int j = 0; j < 4; j++) {
                    const int k = kb + ch * 4 + j;
                    ulonglong2 wv = *(const ulonglong2*)(&ws[k][cg * 4]);
                    float4 va = hA[cur][j], vb = hB[cur][j];
                    ull h2;
                    h2 = pack2(va.x, va.x);
                    acc[0][0] = fma2(h2, wv.x, acc[0][0]);
                    acc[0][1] = fma2(h2, wv.y, acc[0][1]);
                    h2 = pack2(va.y, va.y);
                    acc[1][0] = fma2(h2, wv.x, acc[1][0]);
                    acc[1][1] = fma2(h2, wv.y, acc[1][1]);
                    h2 = pack2(va.z, va.z);
                    acc[2][0] = fma2(h2, wv.x, acc[2][0]);
                    acc[2][1] = fma2(h2, wv.y, acc[2][1]);
                    h2 = pack2(va.w, va.w);
                    acc[3][0] = fma2(h2, wv.x, acc[3][0]);
                    acc[3][1] = fma2(h2, wv.y, acc[3][1]);
                    h2 = pack2(vb.x, vb.x);
                    acc[4][0] = fma2(h2, wv.x, acc[4][0]);
                    acc[4][1] = fma2(h2, wv.y, acc[4][1]);
                    h2 = pack2(vb.y, vb.y);
                    acc[5][0] = fma2(h2, wv.x, acc[5][0]);
                    acc[5][1] = fma2(h2, wv.y, acc[5][1]);
                    h2 = pack2(vb.z, vb.z);
                    acc[6][0] = fma2(h2, wv.x, acc[6][0]);
                    acc[6][1] = fma2(h2, wv.y, acc[6][1]);
                    h2 = pack2(vb.w, vb.w);
                    acc[7][0] = fma2(h2, wv.x, acc[7][0]);
                    acc[7][1] = fma2(h2, wv.y, acc[7][1]);
                }
            }
        }

        // ---- store partials (swizzled) ----
#pragma unroll
        for (int bb = 0; bb < 8; bb++) {
            unsigned off = (unsigned)(((kh * 256 + b0 + bb) * 4 + cg * 2) * 8);
            *(ulonglong2*)((char*)sm_part + swz(off)) =
                make_ulonglong2(acc[bb][0], acc[bb][1]);
        }
        __syncthreads();

        // ---- activation phase: thread = batch b ----
        ull aF = pack2(xA.x, xA.y);
        ull aI = pack2(xA.z, xA.w);
        ull aO = pack2(xB.x, xB.y);
        ull aG = pack2(xB.z, xB.w);
        if (t + 1 < SEQT) {
            const float4* nx = xwp + (size_t)(t + 1) * xw_stride_t;
            xA = __ldcs(nx);
            xB = __ldcs(nx + BATCH);
        }
#pragma unroll
        for (int q = 0; q < 4; q++) {
            unsigned off = (unsigned)(((q * 256 + b) * 4) * 8);
            ulonglong2 v0 = *(const ulonglong2*)((const char*)sm_part + swz(off));
            ulonglong2 v1 = *(const ulonglong2*)((const char*)sm_part + swz(off + 16));
            aF = add2(aF, v0.x);
            aI = add2(aI, v0.y);
            aO = add2(aO, v1.x);
            aG = add2(aG, v1.y);
        }

        float f0, f1, i0, i1, o0, o1, gg0, gg1;
        unpack2(aF, f0, f1); unpack2(aI, i0, i1);
        unpack2(aO, o0, o1); unpack2(aG, gg0, gg1);

        cc0 = sigf(f0) * cc0 + sigf(i0) * tanhf_fast(gg0);
        cc1 = sigf(f1) * cc1 + sigf(i1) * tanhf_fast(gg1);
        float h0 = sigf(o0) * tanhf_fast(cc0);
        float h1 = sigf(o1) * tanhf_fast(cc1);

        // ---- h exchange store (the only data other CTAs read) ----
        float* hw = g_hb[(t + 1) & 1];
        hw[u0 * BATCH + b]       = h0;      // coalesced over b
        hw[(u0 + 1) * BATCH + b] = h1;

        // ---- ARRIVE early: h stores above are drained by the bar.sync, then
        //      thread0's fence orders them before the count increment. ----
        __syncthreads();
        unsigned my_gen = 0;
        bool releaser = false;
        if (tid == 0) {
            volatile unsigned* genp = &g_bar_gen;
            my_gen = *genp;
            __threadfence();
            if (atomicAdd(&g_bar_count, 1u) == NB - 1u) {
                g_bar_count = 0;
                __threadfence();
                *genp = my_gen + 1u;
                releaser = true;
            }
        }

        // ---- output stores overlap other CTAs' arrival + release latency ----
        size_t ob = ((size_t)b * SEQT + t) * HID + u0;
        __stcs((float2*)(outH + ob), make_float2(h0, h1));
        __stcs((float2*)(outC + ob), make_float2(cc0, cc1));

        // ---- WAIT ----
        if (tid == 0 && !releaser) {
            volatile unsigned* genp = &g_bar_gen;
            while (*genp == my_gen) { }
        }
        __syncthreads();
    }

    // ---- final FC: out[bo] = h_last[bo,:] . fc_w + fc_b ----
    const float* hl = g_hb[SEQT & 1];
    float fw = fc_w[tid];
    float fb = fc_b[0];
    for (int bb = 0; bb < 2; bb++) {
        int bo = u0 + bb;
        redf[tid] = __ldcg(hl + tid * BATCH + bo) * fw;   // k = tid
        __syncthreads();
        for (int s = NT / 2; s > 0; s >>= 1) {
            if (tid < s) redf[tid] += redf[tid + s];
            __syncthreads();
        }
        if (tid == 0) outO[bo] = redf[0] + fb;
        __syncthreads();
    }
}

// ============================================================================
extern "C" void kernel_launch(void* const* d_in, const int* in_sizes, int n_in,
                              void* d_out, int out_size) {
    const float* x    = (const float*)d_in[0];  // (256, 365, 32)
    const float* w_ih = (const float*)d_in[1];  // (32, 1024)
    const float* w_hh = (const float*)d_in[2];  // (256, 1024)
    const float* bias = (const float*)d_in[3];  // (1024,)
    const float* fc_w = (const float*)d_in[4];  // (256, 1)
    const float* fc_b = (const float*)d_in[5];  // (1,)
    float* out = (float*)d_out;

    dim3 gA(SEQT, 8);
    xw_kernel<<<gA, NTX>>>(x, w_ih, bias);
    lstm_kernel<<<NB, NT>>>(w_hh, fc_w, fc_b, out);
}